// round 9
// baseline (speedup 1.0000x reference)
#include <cuda_runtime.h>
#include <cstdint>

// ---------------------------------------------------------------------------
// Problem constants
// ---------------------------------------------------------------------------
#define BATCH 4
#define S_LEN 4096
#define HID   1024
#define ADIM  1024
#define NSC   4
#define MTOT  (BATCH * S_LEN)     // 16384 tokens
#define CHUNK 64
#define NCHUNK (S_LEN / CHUNK)    // 64

// ---------------------------------------------------------------------------
// Scratch (static __device__ — no allocations allowed)
// ---------------------------------------------------------------------------
__device__ float g_Pin[MTOT * ADIM];          // after GEMM1: W_in proj; after scanA: u = sig(in)*silu(val)
__device__ float g_Pval[MTOT * ADIM];
__device__ float g_Pq[MTOT * ADIM];
__device__ float g_Pup[MTOT * ADIM];
__device__ float g_Pgate[MTOT * ADIM];
__device__ float g_Z[MTOT * 2048];            // [read | hidden] concat (fp32; rounded in GEMM regs)
__device__ float g_mix[MTOT * NSC];
__device__ float g_carry[BATCH * NCHUNK * ADIM];
__device__ float g_cin[BATCH * NCHUNK * ADIM];

// ---------------------------------------------------------------------------
// Helpers
// ---------------------------------------------------------------------------
__device__ __forceinline__ float sigm(float v) { return 1.f / (1.f + __expf(-v)); }

__device__ __forceinline__ uint32_t tf32u(float v) {
    uint32_t u;
    asm("cvt.rna.tf32.f32 %0, %1;" : "=r"(u) : "f"(v));
    return u;
}

__device__ __forceinline__ void cpasync16(float* smem, const float* gmem) {
    uint32_t s = (uint32_t)__cvta_generic_to_shared(smem);
    asm volatile("cp.async.cg.shared.global [%0], [%1], 16;\n" :: "r"(s), "l"(gmem));
}

// ---------------------------------------------------------------------------
// Per-token mix softmax: logits[n] = x[m] . W_mix[n], softmax over 4
// (x rows read as float4 — coalesced 16B per lane)
// ---------------------------------------------------------------------------
__global__ void k_mix(const float* __restrict__ x, const float* __restrict__ Wm,
                      float* __restrict__ mix) {
    __shared__ float lg[4];
    __shared__ float ex[4];
    int m = blockIdx.x;
    int tid = threadIdx.x;
    int w = tid >> 5, lane = tid & 31;
    const float4* xr = (const float4*)(x + (size_t)m * HID);
    const float4* wr = (const float4*)(Wm + w * HID);
    float s = 0.f;
    #pragma unroll
    for (int h = lane; h < HID / 4; h += 32) {
        float4 a = xr[h];
        float4 b = wr[h];
        s += a.x * b.x + a.y * b.y + a.z * b.z + a.w * b.w;
    }
    #pragma unroll
    for (int o = 16; o; o >>= 1) s += __shfl_xor_sync(0xffffffffu, s, o);
    if (lane == 0) lg[w] = s;
    __syncthreads();
    if (tid < 4) {
        float mx = fmaxf(fmaxf(lg[0], lg[1]), fmaxf(lg[2], lg[3]));
        ex[tid] = __expf(lg[tid] - mx);
    }
    __syncthreads();
    if (tid < 4) {
        float sum = ex[0] + ex[1] + ex[2] + ex[3];
        mix[(size_t)m * 4 + tid] = ex[tid] / sum;
    }
}

// ---------------------------------------------------------------------------
// tf32 GEMM: C = A[M x K] * W[n x k]^T, 128x128x32 tiles,
// cp.async 3-stage pipeline (prefetch distance 2).
// Fragments are rounded fp32->tf32 (RNA) in registers right before the MMA,
// so A and W are the RAW fp32 tensors (no pre-rounding pass needed).
// useN=1: weight/output segment selected by n-tile (n>>10)  [GEMM1, K=1024, N=5120]
// useN=0: weight segment selected by k-tile (k>>10), C[0]   [GEMM2, K=2048, N=1024]
// All weight matrices are 1024x1024 row-major (row = output dim, col = k).
// ---------------------------------------------------------------------------
struct GemmP {
    const float* A;
    const float* W[5];
    float* C[5];
    int K;
    int useN;
};

#define STAGE_F 4096    // floats per stage per operand (128 x 32)
#define NSTAGE 3

__device__ __forceinline__ void g_load_tile(const GemmP& p, int m0, int n0, int k0,
                                            float* As, float* Bs, int tid) {
    const int lr = tid >> 3;       // 0..31 row within pass
    const int lc = tid & 7;        // 0..7  16B group
    const int wsel = p.useN ? (n0 >> 10) : (k0 >> 10);
    const float* Wb = p.W[wsel];
    const int kw = k0 & 1023;
    const float* gaBase = p.A + (size_t)(m0 + lr) * p.K + k0 + lc * 4;
    #pragma unroll
    for (int ps = 0; ps < 4; ps++) {
        int m = ps * 32 + lr;
        float* sa = As + m * 32 + ((lc * 4) ^ ((m & 7) << 2));
        cpasync16(sa, gaBase + (size_t)(ps * 32) * p.K);
    }
    const float* gbBase = Wb + (size_t)((n0 + lr) & 1023) * 1024 + kw + lc * 4;
    #pragma unroll
    for (int ps = 0; ps < 4; ps++) {
        int n = ps * 32 + lr;
        float* sb = Bs + n * 32 + ((lc * 4) ^ ((n & 7) << 2));
        cpasync16(sb, gbBase + (size_t)(ps * 32) * 1024);
    }
}

__device__ __forceinline__ void g_compute(const float* __restrict__ As,
                                          const float* __restrict__ Bs,
                                          float acc[4][4][4],
                                          int wm, int wn, int gr, int tc) {
    #pragma unroll
    for (int kk = 0; kk < 4; kk++) {
        const int k8 = kk * 8;
        uint32_t af[4][4];
        uint32_t bf[4][2];
        #pragma unroll
        for (int i = 0; i < 4; i++) {
            int m = wm + i * 16 + gr;
            int sw = (m & 7) << 2;
            int cA = (k8 + tc) ^ sw;
            int cB = (k8 + tc + 4) ^ sw;
            af[i][0] = tf32u(As[m * 32 + cA]);
            af[i][1] = tf32u(As[(m + 8) * 32 + cA]);
            af[i][2] = tf32u(As[m * 32 + cB]);
            af[i][3] = tf32u(As[(m + 8) * 32 + cB]);
        }
        #pragma unroll
        for (int j = 0; j < 4; j++) {
            int n = wn + j * 8 + gr;
            int sw = (n & 7) << 2;
            bf[j][0] = tf32u(Bs[n * 32 + ((k8 + tc) ^ sw)]);
            bf[j][1] = tf32u(Bs[n * 32 + ((k8 + tc + 4) ^ sw)]);
        }
        #pragma unroll
        for (int i = 0; i < 4; i++) {
            #pragma unroll
            for (int j = 0; j < 4; j++) {
                asm volatile(
                    "mma.sync.aligned.m16n8k8.row.col.f32.tf32.tf32.f32 "
                    "{%0,%1,%2,%3}, {%4,%5,%6,%7}, {%8,%9}, {%0,%1,%2,%3};"
                    : "+f"(acc[i][j][0]), "+f"(acc[i][j][1]),
                      "+f"(acc[i][j][2]), "+f"(acc[i][j][3])
                    : "r"(af[i][0]), "r"(af[i][1]), "r"(af[i][2]), "r"(af[i][3]),
                      "r"(bf[j][0]), "r"(bf[j][1]));
            }
        }
    }
}

__global__ void __launch_bounds__(256) k_gemm(GemmP p) {
    extern __shared__ float sm[];
    float* As = sm;                        // NSTAGE x 128x32
    float* Bs = sm + NSTAGE * STAGE_F;     // NSTAGE x 128x32
    const int tid = threadIdx.x;
    const int n0 = blockIdx.x * 128;
    const int m0 = blockIdx.y * 128;
    const int warp = tid >> 5, lane = tid & 31;
    const int wm = (warp & 1) * 64, wn = (warp >> 1) * 32;
    const int gr = lane >> 2, tc = lane & 3;

    float acc[4][4][4];
    #pragma unroll
    for (int i = 0; i < 4; i++)
        #pragma unroll
        for (int j = 0; j < 4; j++)
            #pragma unroll
            for (int r = 0; r < 4; r++) acc[i][j][r] = 0.f;

    const int nt = p.K >> 5;
    // Prologue: prefetch tiles 0 and 1 into stages 0 and 1 (one group each).
    g_load_tile(p, m0, n0, 0, As, Bs, tid);
    asm volatile("cp.async.commit_group;\n");
    g_load_tile(p, m0, n0, 32, As + STAGE_F, Bs + STAGE_F, tid);
    asm volatile("cp.async.commit_group;\n");

    int st = 0;          // stage holding tile kt
    int stp = 2;         // stage for tile kt+2
    for (int kt = 0; kt < nt; kt++) {
        if (kt + 2 < nt)
            g_load_tile(p, m0, n0, (kt + 2) << 5, As + stp * STAGE_F, Bs + stp * STAGE_F, tid);
        asm volatile("cp.async.commit_group;\n");   // uniform: one group per iter
        asm volatile("cp.async.wait_group 2;\n");   // <=2 pending => tile kt resident
        __syncthreads();
        g_compute(As + st * STAGE_F, Bs + st * STAGE_F, acc, wm, wn, gr, tc);
        __syncthreads();
        st = (st == NSTAGE - 1) ? 0 : st + 1;
        stp = (stp == NSTAGE - 1) ? 0 : stp + 1;
    }

    float* Cb = p.C[p.useN ? (n0 >> 10) : 0];
    #pragma unroll
    for (int i = 0; i < 4; i++) {
        #pragma unroll
        for (int j = 0; j < 4; j++) {
            int row = m0 + wm + i * 16 + gr;
            int col = (n0 + wn + j * 8 + tc * 2) & 1023;
            float2 v01 = make_float2(acc[i][j][0], acc[i][j][1]);
            float2 v23 = make_float2(acc[i][j][2], acc[i][j][3]);
            *(float2*)(Cb + (size_t)row * 1024 + col) = v01;
            *(float2*)(Cb + (size_t)(row + 8) * 1024 + col) = v23;
        }
    }
}

// ---------------------------------------------------------------------------
// Scan pass A (float4): per-(b, chunk, 4-channel group) local carry with zero
// init. Fuses u = sigmoid(Pin)*silu(Pval), stored IN-PLACE over g_Pin
// (same-thread RMW; GEMM1 regenerates g_Pin every launch -> replay-safe).
// grid = BATCH*NCHUNK blocks of 256 threads (each thread = 4 channels)
// ---------------------------------------------------------------------------
__global__ void k_scanA(const float* __restrict__ logit_decay) {
    int bx = blockIdx.x;
    int c = bx & (NCHUNK - 1);
    int b = bx >> 6;                       // log2(NCHUNK)=6
    int a4 = threadIdx.x;                  // float4 channel group 0..255
    float4 ld = ((const float4*)logit_decay)[a4];
    float4 d = make_float4(sigm(ld.x), sigm(ld.y), sigm(ld.z), sigm(ld.w));
    size_t mbase = (size_t)b * S_LEN + (size_t)c * CHUNK;
    size_t off4 = mbase * 256 + a4;        // float4 stride per token = ADIM/4
    float4* Pin4 = (float4*)g_Pin;
    const float4* Pval4 = (const float4*)g_Pval;
    float4 st = make_float4(0.f, 0.f, 0.f, 0.f);
    #pragma unroll 4
    for (int s = 0; s < CHUNK; s++) {
        float4 pin = Pin4[off4];
        float4 pv = Pval4[off4];
        float4 u;
        u.x = sigm(pin.x) * pv.x * sigm(pv.x);
        u.y = sigm(pin.y) * pv.y * sigm(pv.y);
        u.z = sigm(pin.z) * pv.z * sigm(pv.z);
        u.w = sigm(pin.w) * pv.w * sigm(pv.w);
        Pin4[off4] = u;                    // cache u for pass C
        st.x = d.x * st.x + u.x;
        st.y = d.y * st.y + u.y;
        st.z = d.z * st.z + u.z;
        st.w = d.w * st.w + u.w;
        off4 += 256;
    }
    ((float4*)g_carry)[((size_t)b * NCHUNK + c) * 256 + a4] = st;
}

// ---------------------------------------------------------------------------
// Scan pass B: cross-chunk exclusive scan (NCHUNK chunks serial per channel)
// grid = BATCH*4 blocks of 256 threads (scalar; tiny traffic)
// ---------------------------------------------------------------------------
__global__ void k_scanB(const float* __restrict__ logit_decay,
                        const float* __restrict__ init_state) {
    int b = blockIdx.x >> 2;
    int a = (blockIdx.x & 3) * 256 + threadIdx.x;
    float d = sigm(logit_decay[a]);
    float dp = d;
    #pragma unroll
    for (int q = 0; q < 6; q++) dp *= dp;  // d^64 (= d^CHUNK)
    float st = init_state[a];
    #pragma unroll
    for (int c = 0; c < NCHUNK; c++) {
        size_t idx = ((size_t)b * NCHUNK + c) * ADIM + a;
        g_cin[idx] = st;
        st = dp * st + g_carry[idx];
    }
}

// ---------------------------------------------------------------------------
// Scan pass C (float4, + hidden fusion): recompute states with correct
// chunk-entry state (u cached in g_Pin by pass A), emit
// read = silu(q*state)*mix -> Z[:, 0:1024] and hidden = up*silu(gate) ->
// Z[:, 1024:2048] in the same pass (identical (m, a) thread space).
// grid = BATCH*NCHUNK blocks of 256 threads (each thread = 4 channels)
// ---------------------------------------------------------------------------
__global__ void k_scanC(const float* __restrict__ logit_decay) {
    int bx = blockIdx.x;
    int c = bx & (NCHUNK - 1);
    int b = bx >> 6;
    int a4 = threadIdx.x;
    int ns = a4 >> 6;                      // (4*a4)>>8; uniform over the 4 channels
    float4 ld = ((const float4*)logit_decay)[a4];
    float4 d = make_float4(sigm(ld.x), sigm(ld.y), sigm(ld.z), sigm(ld.w));
    size_t mbase = (size_t)b * S_LEN + (size_t)c * CHUNK;
    size_t off4 = mbase * 256 + a4;
    const float4* Pin4 = (const float4*)g_Pin;
    const float4* Pq4 = (const float4*)g_Pq;
    const float4* Pup4 = (const float4*)g_Pup;
    const float4* Pgt4 = (const float4*)g_Pgate;
    float4* Z4 = (float4*)g_Z;
    float4 st = ((const float4*)g_cin)[((size_t)b * NCHUNK + c) * 256 + a4];
    #pragma unroll 4
    for (int s = 0; s < CHUNK; s++) {
        size_t m = mbase + s;
        float4 u = Pin4[off4];             // precomputed by pass A
        st.x = d.x * st.x + u.x;
        st.y = d.y * st.y + u.y;
        st.z = d.z * st.z + u.z;
        st.w = d.w * st.w + u.w;
        float4 q = Pq4[off4];
        float mv = g_mix[m * 4 + ns];
        float4 rd;
        float r;
        r = q.x * st.x; rd.x = r * sigm(r) * mv;
        r = q.y * st.y; rd.y = r * sigm(r) * mv;
        r = q.z * st.z; rd.z = r * sigm(r) * mv;
        r = q.w * st.w; rd.w = r * sigm(r) * mv;
        Z4[m * 512 + a4] = rd;             // read (rounded to tf32 inside GEMM2)
        float4 up = Pup4[off4];
        float4 gt = Pgt4[off4];
        float4 h;
        h.x = up.x * gt.x * sigm(gt.x);
        h.y = up.y * gt.y * sigm(gt.y);
        h.z = up.z * gt.z * sigm(gt.z);
        h.w = up.w * gt.w * sigm(gt.w);
        Z4[m * 512 + 256 + a4] = h;        // hidden
        off4 += 256;
    }
}

// ---------------------------------------------------------------------------
// Launch
// ---------------------------------------------------------------------------
extern "C" void kernel_launch(void* const* d_in, const int* in_sizes, int n_in,
                              void* d_out, int out_size) {
    const float* x       = (const float*)d_in[0];
    const float* W_in    = (const float*)d_in[1];
    const float* W_val   = (const float*)d_in[2];
    const float* W_q     = (const float*)d_in[3];
    const float* W_mix   = (const float*)d_in[4];
    const float* W_rout  = (const float*)d_in[5];
    const float* W_up    = (const float*)d_in[6];
    const float* W_gate  = (const float*)d_in[7];
    const float* W_down  = (const float*)d_in[8];
    const float* logit_decay   = (const float*)d_in[9];
    const float* initial_state = (const float*)d_in[10];
    float* out = (float*)d_out;

    float *p_Pin, *p_Pval, *p_Pq, *p_Pup, *p_Pgate, *p_Z, *p_mix;
    cudaGetSymbolAddress((void**)&p_Pin, g_Pin);
    cudaGetSymbolAddress((void**)&p_Pval, g_Pval);
    cudaGetSymbolAddress((void**)&p_Pq, g_Pq);
    cudaGetSymbolAddress((void**)&p_Pup, g_Pup);
    cudaGetSymbolAddress((void**)&p_Pgate, g_Pgate);
    cudaGetSymbolAddress((void**)&p_Z, g_Z);
    cudaGetSymbolAddress((void**)&p_mix, g_mix);

    const int SMEM_GEMM = NSTAGE * STAGE_F * 2 * (int)sizeof(float);  // 98304

    // 1) mix softmax
    k_mix<<<MTOT, 128>>>(x, W_mix, p_mix);

    // 2) GEMM1: [Pin|Pval|Pq|Pup|Pgate] = x @ Wseg^T, N=5120, K=1024
    //    (fragments rounded to tf32 in registers)
    cudaFuncSetAttribute(k_gemm, cudaFuncAttributeMaxDynamicSharedMemorySize, SMEM_GEMM);
    {
        GemmP p;
        p.A = x;
        p.W[0] = W_in;
        p.W[1] = W_val;
        p.W[2] = W_q;
        p.W[3] = W_up;
        p.W[4] = W_gate;
        p.C[0] = p_Pin; p.C[1] = p_Pval; p.C[2] = p_Pq; p.C[3] = p_Pup; p.C[4] = p_Pgate;
        p.K = 1024;
        p.useN = 1;
        k_gemm<<<dim3(40, 128), 256, SMEM_GEMM>>>(p);
    }

    // 3) chunked linear-recurrence scan + read/hidden emission
    k_scanA<<<BATCH * NCHUNK, 256>>>(logit_decay);
    k_scanB<<<BATCH * 4, 256>>>(logit_decay, initial_state);
    k_scanC<<<BATCH * NCHUNK, 256>>>(logit_decay);

    // 4) GEMM2: out = Z @ [W_rout ; W_down]^T, N=1024, K=2048 (k-segmented)
    {
        GemmP p;
        p.A = p_Z;
        p.W[0] = W_rout;                  // k < 1024
        p.W[1] = W_down;                  // k >= 1024
        p.W[2] = p.W[3] = p.W[4] = nullptr;
        p.C[0] = out;
        p.C[1] = p.C[2] = p.C[3] = p.C[4] = nullptr;
        p.K = 2048;
        p.useN = 0;
        k_gemm<<<dim3(8, 128), 256, SMEM_GEMM>>>(p);
    }
}

// round 10
// speedup vs baseline: 1.1131x; 1.1131x over previous
#include <cuda_runtime.h>
#include <cstdint>

// ---------------------------------------------------------------------------
// Problem constants
// ---------------------------------------------------------------------------
#define BATCH 4
#define S_LEN 4096
#define HID   1024
#define ADIM  1024
#define NSC   4
#define MTOT  (BATCH * S_LEN)     // 16384 tokens
#define CHUNK 64
#define NCHUNK (S_LEN / CHUNK)    // 64

// ---------------------------------------------------------------------------
// Scratch (static __device__ — no allocations allowed)
// ---------------------------------------------------------------------------
__device__ float g_Pin[MTOT * ADIM];          // after GEMM1: W_in proj; after scanA: u
__device__ float g_Pval[MTOT * ADIM];
__device__ float g_Pq[MTOT * ADIM];
__device__ float g_Pup[MTOT * ADIM];
__device__ float g_Pgate[MTOT * ADIM];
__device__ float g_Z[MTOT * 2048];            // [read | hidden] concat
__device__ float g_mix[MTOT * NSC];
__device__ float g_carry[BATCH * NCHUNK * ADIM];
__device__ float g_cin[BATCH * NCHUNK * ADIM];

// ---------------------------------------------------------------------------
// Helpers
// ---------------------------------------------------------------------------
__device__ __forceinline__ float sigm(float v) { return 1.f / (1.f + __expf(-v)); }

__device__ __forceinline__ uint32_t tf32u(float v) {
    uint32_t u;
    asm("cvt.rna.tf32.f32 %0, %1;" : "=r"(u) : "f"(v));
    return u;
}

__device__ __forceinline__ void cpasync16(float* smem, const float* gmem) {
    uint32_t s = (uint32_t)__cvta_generic_to_shared(smem);
    asm volatile("cp.async.cg.shared.global [%0], [%1], 16;\n" :: "r"(s), "l"(gmem));
}

// ---------------------------------------------------------------------------
// Per-token mix softmax over a token range (split into 3 launches so the ncu
// capture slot lands on GEMM1).
// ---------------------------------------------------------------------------
__global__ void k_mix(const float* __restrict__ x, const float* __restrict__ Wm,
                      float* __restrict__ mix, int mbase) {
    __shared__ float lg[4];
    __shared__ float ex[4];
    int m = mbase + blockIdx.x;
    int tid = threadIdx.x;
    int w = tid >> 5, lane = tid & 31;
    const float4* xr = (const float4*)(x + (size_t)m * HID);
    const float4* wr = (const float4*)(Wm + w * HID);
    float s = 0.f;
    #pragma unroll
    for (int h = lane; h < HID / 4; h += 32) {
        float4 a = xr[h];
        float4 b = wr[h];
        s += a.x * b.x + a.y * b.y + a.z * b.z + a.w * b.w;
    }
    #pragma unroll
    for (int o = 16; o; o >>= 1) s += __shfl_xor_sync(0xffffffffu, s, o);
    if (lane == 0) lg[w] = s;
    __syncthreads();
    if (tid < 4) {
        float mx = fmaxf(fmaxf(lg[0], lg[1]), fmaxf(lg[2], lg[3]));
        ex[tid] = __expf(lg[tid] - mx);
    }
    __syncthreads();
    if (tid < 4) {
        float sum = ex[0] + ex[1] + ex[2] + ex[3];
        mix[(size_t)m * 4 + tid] = ex[tid] / sum;
    }
}

// ---------------------------------------------------------------------------
// tf32 GEMM: C = A[M x K] * W[n x k]^T, 256x128x32 tiles, 256 threads,
// 8 warps of 64x64 warp tiles (4x2), cp.async 3-stage pipeline.
// Fragments rounded fp32->tf32 (RNA) in registers before the MMA.
// useN=1: weight/output segment selected by n-tile (n>>10)  [GEMM1]
// useN=0: weight segment selected by k-tile (k>>10), C[0]   [GEMM2]
// Weight matrices are 1024x1024 row-major (row = out dim, col = k).
// ---------------------------------------------------------------------------
struct GemmP {
    const float* A;
    const float* W[5];
    float* C[5];
    int K;
    int useN;
};

#define BM 256
#define BN 128
#define STAGE_A 8192   // 256x32 floats
#define STAGE_B 4096   // 128x32 floats
#define NSTAGE 3

__device__ __forceinline__ void g_load_tile(const GemmP& p, int m0, int n0, int k0,
                                            float* As, float* Bs, int tid) {
    const int lr = tid >> 3;       // 0..31 row within pass
    const int lc = tid & 7;        // 0..7  16B group
    const int wsel = p.useN ? (n0 >> 10) : (k0 >> 10);
    const float* Wb = p.W[wsel];
    const int kw = k0 & 1023;
    const float* gaBase = p.A + (size_t)(m0 + lr) * p.K + k0 + lc * 4;
    #pragma unroll
    for (int ps = 0; ps < 8; ps++) {          // 256 A rows
        int m = ps * 32 + lr;
        float* sa = As + m * 32 + ((lc * 4) ^ ((m & 7) << 2));
        cpasync16(sa, gaBase + (size_t)(ps * 32) * p.K);
    }
    const float* gbBase = Wb + (size_t)((n0 + lr) & 1023) * 1024 + kw + lc * 4;
    #pragma unroll
    for (int ps = 0; ps < 4; ps++) {          // 128 B rows
        int n = ps * 32 + lr;
        float* sb = Bs + n * 32 + ((lc * 4) ^ ((n & 7) << 2));
        cpasync16(sb, gbBase + (size_t)(ps * 32) * 1024);
    }
}

__device__ __forceinline__ void g_compute(const float* __restrict__ As,
                                          const float* __restrict__ Bs,
                                          float acc[4][8][4],
                                          int wm, int wn, int gr, int tc) {
    #pragma unroll
    for (int kk = 0; kk < 4; kk++) {
        const int k8 = kk * 8;
        uint32_t af[4][4];
        uint32_t bf[8][2];
        #pragma unroll
        for (int i = 0; i < 4; i++) {
            int m = wm + i * 16 + gr;
            int sw = (m & 7) << 2;
            int cA = (k8 + tc) ^ sw;
            int cB = (k8 + tc + 4) ^ sw;
            af[i][0] = tf32u(As[m * 32 + cA]);
            af[i][1] = tf32u(As[(m + 8) * 32 + cA]);
            af[i][2] = tf32u(As[m * 32 + cB]);
            af[i][3] = tf32u(As[(m + 8) * 32 + cB]);
        }
        #pragma unroll
        for (int j = 0; j < 8; j++) {
            int n = wn + j * 8 + gr;
            int sw = (n & 7) << 2;
            bf[j][0] = tf32u(Bs[n * 32 + ((k8 + tc) ^ sw)]);
            bf[j][1] = tf32u(Bs[n * 32 + ((k8 + tc + 4) ^ sw)]);
        }
        #pragma unroll
        for (int i = 0; i < 4; i++) {
            #pragma unroll
            for (int j = 0; j < 8; j++) {
                asm volatile(
                    "mma.sync.aligned.m16n8k8.row.col.f32.tf32.tf32.f32 "
                    "{%0,%1,%2,%3}, {%4,%5,%6,%7}, {%8,%9}, {%0,%1,%2,%3};"
                    : "+f"(acc[i][j][0]), "+f"(acc[i][j][1]),
                      "+f"(acc[i][j][2]), "+f"(acc[i][j][3])
                    : "r"(af[i][0]), "r"(af[i][1]), "r"(af[i][2]), "r"(af[i][3]),
                      "r"(bf[j][0]), "r"(bf[j][1]));
            }
        }
    }
}

__global__ void __launch_bounds__(256, 1) k_gemm(GemmP p) {
    extern __shared__ float sm[];
    float* As = sm;                        // NSTAGE x 256x32
    float* Bs = sm + NSTAGE * STAGE_A;     // NSTAGE x 128x32
    const int tid = threadIdx.x;
    const int n0 = blockIdx.x * BN;
    const int m0 = blockIdx.y * BM;
    const int warp = tid >> 5, lane = tid & 31;
    const int wm = (warp & 3) * 64, wn = (warp >> 2) * 64;
    const int gr = lane >> 2, tc = lane & 3;

    float acc[4][8][4];
    #pragma unroll
    for (int i = 0; i < 4; i++)
        #pragma unroll
        for (int j = 0; j < 8; j++)
            #pragma unroll
            for (int r = 0; r < 4; r++) acc[i][j][r] = 0.f;

    const int nt = p.K >> 5;
    g_load_tile(p, m0, n0, 0, As, Bs, tid);
    asm volatile("cp.async.commit_group;\n");
    g_load_tile(p, m0, n0, 32, As + STAGE_A, Bs + STAGE_B, tid);
    asm volatile("cp.async.commit_group;\n");

    int st = 0;          // stage holding tile kt
    int stp = 2;         // stage for tile kt+2
    for (int kt = 0; kt < nt; kt++) {
        if (kt + 2 < nt)
            g_load_tile(p, m0, n0, (kt + 2) << 5, As + stp * STAGE_A, Bs + stp * STAGE_B, tid);
        asm volatile("cp.async.commit_group;\n");   // uniform: one group per iter
        asm volatile("cp.async.wait_group 2;\n");   // <=2 pending => tile kt resident
        __syncthreads();
        g_compute(As + st * STAGE_A, Bs + st * STAGE_B, acc, wm, wn, gr, tc);
        __syncthreads();
        st = (st == NSTAGE - 1) ? 0 : st + 1;
        stp = (stp == NSTAGE - 1) ? 0 : stp + 1;
    }

    float* Cb = p.C[p.useN ? (n0 >> 10) : 0];
    #pragma unroll
    for (int i = 0; i < 4; i++) {
        #pragma unroll
        for (int j = 0; j < 8; j++) {
            int row = m0 + wm + i * 16 + gr;
            int col = (n0 + wn + j * 8 + tc * 2) & 1023;
            float2 v01 = make_float2(acc[i][j][0], acc[i][j][1]);
            float2 v23 = make_float2(acc[i][j][2], acc[i][j][3]);
            *(float2*)(Cb + (size_t)row * 1024 + col) = v01;
            *(float2*)(Cb + (size_t)(row + 8) * 1024 + col) = v23;
        }
    }
}

// ---------------------------------------------------------------------------
// Scan pass A (float4): per-(b, chunk, 4-channel group) local carry, zero init.
// Fuses u = sigmoid(Pin)*silu(Pval) in-place over g_Pin (same-thread RMW;
// regenerated by GEMM1 each launch -> replay-safe).
// ---------------------------------------------------------------------------
__global__ void k_scanA(const float* __restrict__ logit_decay) {
    int bx = blockIdx.x;
    int c = bx & (NCHUNK - 1);
    int b = bx >> 6;
    int a4 = threadIdx.x;
    float4 ld = ((const float4*)logit_decay)[a4];
    float4 d = make_float4(sigm(ld.x), sigm(ld.y), sigm(ld.z), sigm(ld.w));
    size_t mbase = (size_t)b * S_LEN + (size_t)c * CHUNK;
    size_t off4 = mbase * 256 + a4;
    float4* Pin4 = (float4*)g_Pin;
    const float4* Pval4 = (const float4*)g_Pval;
    float4 st = make_float4(0.f, 0.f, 0.f, 0.f);
    #pragma unroll 4
    for (int s = 0; s < CHUNK; s++) {
        float4 pin = Pin4[off4];
        float4 pv = Pval4[off4];
        float4 u;
        u.x = sigm(pin.x) * pv.x * sigm(pv.x);
        u.y = sigm(pin.y) * pv.y * sigm(pv.y);
        u.z = sigm(pin.z) * pv.z * sigm(pv.z);
        u.w = sigm(pin.w) * pv.w * sigm(pv.w);
        Pin4[off4] = u;
        st.x = d.x * st.x + u.x;
        st.y = d.y * st.y + u.y;
        st.z = d.z * st.z + u.z;
        st.w = d.w * st.w + u.w;
        off4 += 256;
    }
    ((float4*)g_carry)[((size_t)b * NCHUNK + c) * 256 + a4] = st;
}

// ---------------------------------------------------------------------------
// Scan pass B: cross-chunk exclusive scan. Load ALL carries first (MLP=64),
// then run the serial recurrence — kills the 600-cycle-per-iter load stalls
// ncu showed (32us -> ~3us predicted).
// ---------------------------------------------------------------------------
__global__ void k_scanB(const float* __restrict__ logit_decay,
                        const float* __restrict__ init_state) {
    int b = blockIdx.x >> 2;
    int a = (blockIdx.x & 3) * 256 + threadIdx.x;
    float d = sigm(logit_decay[a]);
    float dp = d;
    #pragma unroll
    for (int q = 0; q < 6; q++) dp *= dp;  // d^64 (= d^CHUNK)
    float car[NCHUNK];
    #pragma unroll
    for (int c = 0; c < NCHUNK; c++)
        car[c] = g_carry[((size_t)b * NCHUNK + c) * ADIM + a];
    float st = init_state[a];
    #pragma unroll
    for (int c = 0; c < NCHUNK; c++) {
        g_cin[((size_t)b * NCHUNK + c) * ADIM + a] = st;
        st = dp * st + car[c];
    }
}

// ---------------------------------------------------------------------------
// Scan pass C (float4 + hidden fusion): recompute states with correct
// chunk-entry state, emit read -> Z[:,0:1024] and hidden -> Z[:,1024:2048].
// ---------------------------------------------------------------------------
__global__ void k_scanC(const float* __restrict__ logit_decay) {
    int bx = blockIdx.x;
    int c = bx & (NCHUNK - 1);
    int b = bx >> 6;
    int a4 = threadIdx.x;
    int ns = a4 >> 6;
    float4 ld = ((const float4*)logit_decay)[a4];
    float4 d = make_float4(sigm(ld.x), sigm(ld.y), sigm(ld.z), sigm(ld.w));
    size_t mbase = (size_t)b * S_LEN + (size_t)c * CHUNK;
    size_t off4 = mbase * 256 + a4;
    const float4* Pin4 = (const float4*)g_Pin;
    const float4* Pq4 = (const float4*)g_Pq;
    const float4* Pup4 = (const float4*)g_Pup;
    const float4* Pgt4 = (const float4*)g_Pgate;
    float4* Z4 = (float4*)g_Z;
    float4 st = ((const float4*)g_cin)[((size_t)b * NCHUNK + c) * 256 + a4];
    #pragma unroll 4
    for (int s = 0; s < CHUNK; s++) {
        size_t m = mbase + s;
        float4 u = Pin4[off4];
        st.x = d.x * st.x + u.x;
        st.y = d.y * st.y + u.y;
        st.z = d.z * st.z + u.z;
        st.w = d.w * st.w + u.w;
        float4 q = Pq4[off4];
        float mv = g_mix[m * 4 + ns];
        float4 rd;
        float r;
        r = q.x * st.x; rd.x = r * sigm(r) * mv;
        r = q.y * st.y; rd.y = r * sigm(r) * mv;
        r = q.z * st.z; rd.z = r * sigm(r) * mv;
        r = q.w * st.w; rd.w = r * sigm(r) * mv;
        Z4[m * 512 + a4] = rd;
        float4 up = Pup4[off4];
        float4 gt = Pgt4[off4];
        float4 h;
        h.x = up.x * gt.x * sigm(gt.x);
        h.y = up.y * gt.y * sigm(gt.y);
        h.z = up.z * gt.z * sigm(gt.z);
        h.w = up.w * gt.w * sigm(gt.w);
        Z4[m * 512 + 256 + a4] = h;
        off4 += 256;
    }
}

// ---------------------------------------------------------------------------
// Launch
// ---------------------------------------------------------------------------
extern "C" void kernel_launch(void* const* d_in, const int* in_sizes, int n_in,
                              void* d_out, int out_size) {
    const float* x       = (const float*)d_in[0];
    const float* W_in    = (const float*)d_in[1];
    const float* W_val   = (const float*)d_in[2];
    const float* W_q     = (const float*)d_in[3];
    const float* W_mix   = (const float*)d_in[4];
    const float* W_rout  = (const float*)d_in[5];
    const float* W_up    = (const float*)d_in[6];
    const float* W_gate  = (const float*)d_in[7];
    const float* W_down  = (const float*)d_in[8];
    const float* logit_decay   = (const float*)d_in[9];
    const float* initial_state = (const float*)d_in[10];
    float* out = (float*)d_out;

    float *p_Pin, *p_Pval, *p_Pq, *p_Pup, *p_Pgate, *p_Z, *p_mix;
    cudaGetSymbolAddress((void**)&p_Pin, g_Pin);
    cudaGetSymbolAddress((void**)&p_Pval, g_Pval);
    cudaGetSymbolAddress((void**)&p_Pq, g_Pq);
    cudaGetSymbolAddress((void**)&p_Pup, g_Pup);
    cudaGetSymbolAddress((void**)&p_Pgate, g_Pgate);
    cudaGetSymbolAddress((void**)&p_Z, g_Z);
    cudaGetSymbolAddress((void**)&p_mix, g_mix);

    const int SMEM_GEMM = NSTAGE * (STAGE_A + STAGE_B) * (int)sizeof(float); // 147456

    // 1) mix softmax — split in 3 so the fixed ncu capture slot (4th of our
    //    launches) lands on GEMM1.
    k_mix<<<5461, 128>>>(x, W_mix, p_mix, 0);
    k_mix<<<5461, 128>>>(x, W_mix, p_mix, 5461);
    k_mix<<<5462, 128>>>(x, W_mix, p_mix, 10922);

    // 2) GEMM1: [Pin|Pval|Pq|Pup|Pgate] = x @ Wseg^T, N=5120, K=1024
    cudaFuncSetAttribute(k_gemm, cudaFuncAttributeMaxDynamicSharedMemorySize, SMEM_GEMM);
    {
        GemmP p;
        p.A = x;
        p.W[0] = W_in;
        p.W[1] = W_val;
        p.W[2] = W_q;
        p.W[3] = W_up;
        p.W[4] = W_gate;
        p.C[0] = p_Pin; p.C[1] = p_Pval; p.C[2] = p_Pq; p.C[3] = p_Pup; p.C[4] = p_Pgate;
        p.K = 1024;
        p.useN = 1;
        k_gemm<<<dim3(40, 64), 256, SMEM_GEMM>>>(p);
    }

    // 3) chunked linear-recurrence scan + read/hidden emission
    k_scanA<<<BATCH * NCHUNK, 256>>>(logit_decay);
    k_scanB<<<BATCH * 4, 256>>>(logit_decay, initial_state);
    k_scanC<<<BATCH * NCHUNK, 256>>>(logit_decay);

    // 4) GEMM2: out = Z @ [W_rout ; W_down]^T, N=1024, K=2048 (k-segmented)
    {
        GemmP p;
        p.A = p_Z;
        p.W[0] = W_rout;                  // k < 1024
        p.W[1] = W_down;                  // k >= 1024
        p.W[2] = p.W[3] = p.W[4] = nullptr;
        p.C[0] = out;
        p.C[1] = p.C[2] = p.C[3] = p.C[4] = nullptr;
        p.K = 2048;
        p.useN = 0;
        k_gemm<<<dim3(8, 64), 256, SMEM_GEMM>>>(p);
    }
}